// round 14
// baseline (speedup 1.0000x reference)
#include <cuda_runtime.h>
#include <cuda_fp16.h>

#define NS 2048
#define NC 4096
#define NG 2048
#define D  256
#define NH 8
#define TT 4097   // 1 + NS + NG
#define SA0_BLOCKS 32

// ---------------- device scratch ----------------
__device__ float  g_HS[NS * D];
__device__ float  g_HC[NC * D];
__device__ __half g_Qh[NS * D];
__device__ __half g_Kh[NC * D];
__device__ __half g_Vh[NC * D];
__device__ __half g_Gh[(size_t)NS * NC];   // gate * (isq*log2e), fp16
__device__ float  g_Z[NS * NH];
__device__ float  g_Hnew[NS * D];
__device__ float  g_tmp[NS * D];
__device__ float  g_tok[TT * D];
__device__ float  g_k2[TT * D];
__device__ float  g_v2[TT * D];
__device__ float  g_a0p[SA0_BLOCKS][D];
__device__ float  g_Z0p[SA0_BLOCKS][NH];

__device__ __forceinline__ float warpSum(float v) {
#pragma unroll
    for (int o = 16; o; o >>= 1) v += __shfl_xor_sync(0xffffffffu, v, o);
    return v;
}

__device__ __forceinline__ void mma16816(float* c, const unsigned* a, const unsigned* b) {
    asm volatile(
        "mma.sync.aligned.m16n8k16.row.col.f32.f16.f16.f32 "
        "{%0,%1,%2,%3}, {%4,%5,%6,%7}, {%8,%9}, {%0,%1,%2,%3};\n"
        : "+f"(c[0]), "+f"(c[1]), "+f"(c[2]), "+f"(c[3])
        : "r"(a[0]), "r"(a[1]), "r"(a[2]), "r"(a[3]), "r"(b[0]), "r"(b[1]));
}

__device__ __forceinline__ unsigned smaddr(const void* p) {
    return (unsigned)__cvta_generic_to_shared(p);
}
__device__ __forceinline__ void ldm_x2(unsigned& r0, unsigned& r1, unsigned a) {
    asm volatile("ldmatrix.sync.aligned.m8n8.x2.shared.b16 {%0,%1}, [%2];"
                 : "=r"(r0), "=r"(r1) : "r"(a));
}
__device__ __forceinline__ void ldm_x2_t(unsigned& r0, unsigned& r1, unsigned a) {
    asm volatile("ldmatrix.sync.aligned.m8n8.x2.trans.shared.b16 {%0,%1}, [%2];"
                 : "=r"(r0), "=r"(r1) : "r"(a));
}
__device__ __forceinline__ void ldm_x4(unsigned* r, unsigned a) {
    asm volatile("ldmatrix.sync.aligned.m8n8.x4.shared.b16 {%0,%1,%2,%3}, [%4];"
                 : "=r"(r[0]), "=r"(r[1]), "=r"(r[2]), "=r"(r[3]) : "r"(a));
}
__device__ __forceinline__ void cpa16(void* smem, const void* gmem) {
    asm volatile("cp.async.cg.shared.global [%0], [%1], 16;"
                 :: "r"(smaddr(smem)), "l"(gmem));
}
__device__ __forceinline__ __half2 h2ex2(__half2 x) {
    unsigned r, xi = *(unsigned*)&x;
    asm("ex2.approx.f16x2 %0, %1;" : "=r"(r) : "r"(xi));
    return *(__half2*)&r;
}

#define CE 0.25506382f   // (1/sqrt(32)) * log2(e)

// ---------------- fp16 tensor-core GEMM, register-prefetch pipelined ----------------
// Up to 3 problems via blockIdx.z (per-z K). If gsrc != null, LAST z-slice = gate conversion.
template<int OM>
__global__ __launch_bounds__(256) void gemm16_kernel(
    const float* __restrict__ A0, const float* __restrict__ W0, const float* __restrict__ bs0,
    float* __restrict__ Cf0, __half* __restrict__ Ch0, int M0,
    const float* __restrict__ A1, const float* __restrict__ W1, const float* __restrict__ bs1,
    float* __restrict__ Cf1, __half* __restrict__ Ch1, int M1,
    const float* __restrict__ A2, const float* __restrict__ W2, const float* __restrict__ bs2,
    float* __restrict__ Cf2, __half* __restrict__ Ch2, int M2,
    int N, int K0p, int K1p, int K2p,
    const float* __restrict__ gsrc, __half* __restrict__ gdst)
{
    if (gsrc != nullptr && blockIdx.z == gridDim.z - 1) {
        int bid = blockIdx.y * gridDim.x + blockIdx.x;
        int t4 = bid * 256 + threadIdx.x;
        const int total4 = (NS * NC) / 4;
        int stride = gridDim.x * gridDim.y * 256;
        for (int i = t4; i < total4; i += stride) {
            float4 v = *(const float4*)&gsrc[(size_t)i * 4];
            __half2 h0 = __floats2half2_rn(v.x * CE, v.y * CE);
            __half2 h1 = __floats2half2_rn(v.z * CE, v.w * CE);
            *(int2*)&gdst[(size_t)i * 4] = make_int2(*(int*)&h0, *(int*)&h1);
        }
        return;
    }

    const int z = blockIdx.z;
    const float* A    = z == 0 ? A0  : (z == 1 ? A1  : A2);
    const float* W    = z == 0 ? W0  : (z == 1 ? W1  : W2);
    const float* bias = z == 0 ? bs0 : (z == 1 ? bs1 : bs2);
    float* Cf         = z == 0 ? Cf0 : (z == 1 ? Cf1 : Cf2);
    __half* Ch        = z == 0 ? Ch0 : (z == 1 ? Ch1 : Ch2);
    const int M       = z == 0 ? M0  : (z == 1 ? M1  : M2);
    const int K       = z == 0 ? K0p : (z == 1 ? K1p : K2p);

    const int bm = blockIdx.y * 64, bn = blockIdx.x * 64;
    if (bm >= M) return;

    __shared__ __half Ah[64 * 40];
    __shared__ __half Bh[64 * 40];

    const int tid = threadIdx.x;
    const int w = tid >> 5, lane = tid & 31;
    const int wr = w >> 1, wc = w & 1;
    const int gr = lane >> 2, cc = lane & 3;
    const int fr = tid >> 2, fc8 = (tid & 3) * 8;
    const int l4 = lane & 15;
    const int hi8 = (lane >> 4) * 8;
    const bool aval = (bm + fr < M);

    float acc[4][4] = {};
    const int nCh = K >> 5;

    // register prefetch buffers
    float4 pa0, pa1, pb0, pb1;
    auto loadrg = [&](int k0) {
        pa0 = make_float4(0.f, 0.f, 0.f, 0.f); pa1 = pa0;
        if (aval) {
            const float* ap = &A[(size_t)(bm + fr) * K + k0 + fc8];
            pa0 = *(const float4*)ap;
            pa1 = *(const float4*)(ap + 4);
        }
        const float* wp = &W[(size_t)(bn + fr) * K + k0 + fc8];
        pb0 = *(const float4*)wp;
        pb1 = *(const float4*)(wp + 4);
    };

    loadrg(0);
    for (int ch = 0; ch < nCh; ch++) {
        __syncthreads();   // previous mma phase done reading smem
        {
            __half2 h0 = __floats2half2_rn(pa0.x, pa0.y);
            __half2 h1 = __floats2half2_rn(pa0.z, pa0.w);
            __half2 h2 = __floats2half2_rn(pa1.x, pa1.y);
            __half2 h3 = __floats2half2_rn(pa1.z, pa1.w);
            *(int4*)&Ah[fr * 40 + fc8] = make_int4(*(int*)&h0, *(int*)&h1, *(int*)&h2, *(int*)&h3);
            __half2 g0 = __floats2half2_rn(pb0.x, pb0.y);
            __half2 g1 = __floats2half2_rn(pb0.z, pb0.w);
            __half2 g2 = __floats2half2_rn(pb1.x, pb1.y);
            __half2 g3 = __floats2half2_rn(pb1.z, pb1.w);
            *(int4*)&Bh[fr * 40 + fc8] = make_int4(*(int*)&g0, *(int*)&g1, *(int*)&g2, *(int*)&g3);
        }
        __syncthreads();
        // issue next chunk's global loads early (overlap with mma below)
        if (ch + 1 < nCh) loadrg((ch + 1) << 5);

#pragma unroll
        for (int ks = 0; ks < 2; ks++) {
            unsigned af[4];
            ldm_x4(af, smaddr(&Ah[(wr * 16 + l4) * 40 + ks * 16 + hi8]));
            unsigned bf[2][4];
#pragma unroll
            for (int p = 0; p < 2; p++)
                ldm_x4(bf[p], smaddr(&Bh[(wc * 32 + p * 16 + l4) * 40 + ks * 16 + hi8]));
#pragma unroll
            for (int nt = 0; nt < 4; nt++) {
                unsigned bb[2];
                bb[0] = bf[nt >> 1][(nt & 1)];
                bb[1] = bf[nt >> 1][(nt & 1) + 2];
                mma16816(acc[nt], af, bb);
            }
        }
    }

#pragma unroll
    for (int nt = 0; nt < 4; nt++) {
        int col = bn + wc * 32 + nt * 8 + 2 * cc;
        float b0 = bias ? bias[col] : 0.f;
        float b1 = bias ? bias[col + 1] : 0.f;
        int row0 = bm + wr * 16 + gr;
        int row1 = row0 + 8;
        if (row0 < M) {
            if (OM == 1) {
                Ch[(size_t)row0 * N + col]     = __float2half(acc[nt][0] + b0);
                Ch[(size_t)row0 * N + col + 1] = __float2half(acc[nt][1] + b1);
            } else {
                Cf[(size_t)row0 * N + col]     = acc[nt][0] + b0;
                Cf[(size_t)row0 * N + col + 1] = acc[nt][1] + b1;
            }
        }
        if (row1 < M) {
            if (OM == 1) {
                Ch[(size_t)row1 * N + col]     = __float2half(acc[nt][2] + b0);
                Ch[(size_t)row1 * N + col + 1] = __float2half(acc[nt][3] + b1);
            } else {
                Cf[(size_t)row1 * N + col]     = acc[nt][2] + b0;
                Cf[(size_t)row1 * N + col + 1] = acc[nt][3] + b1;
            }
        }
    }
}

// ---------------- fused gated cross-attention: 32 s-rows per block, Z via mma ----------------
#define CA_SMEM 105600
__global__ __launch_bounds__(256, 2) void ca_fused_kernel()
{
    extern __shared__ __align__(16) char smraw[];
    __half* Ks  = (__half*)smraw;
    __half* Vs  = (__half*)(smraw + 40960);
    __half* Ghs = (__half*)(smraw + 81920);
    __half* Qs  = (__half*)(smraw + 98816);
    float*  Hs  = (float*)(smraw + 101376);
    float*  Zs  = (float*)(smraw + 105472);

    const int h = blockIdx.x;
    const int s0 = blockIdx.y * 32;
    const int tid = threadIdx.x;
    const int w = tid >> 5, lane = tid & 31;
    const int gr = lane >> 2, cc = lane & 3;
    const int cw = w * 32;
    const int l4 = lane & 15;

    auto issue_tile = [&](int ci) {
        int buf = (ci & 1) * 10240;
        int c0 = ci * 256;
        int pr = tid >> 2, pp4 = tid & 3;
#pragma unroll
        for (int rr = 0; rr < 4; rr++) {
            int row = rr * 64 + pr;
            size_t src = (size_t)(c0 + row) * D + h * 32 + pp4 * 8;
            cpa16(&Ks[buf + row * 40 + pp4 * 8], &g_Kh[src]);
            cpa16(&Vs[buf + row * 40 + pp4 * 8], &g_Vh[src]);
        }
#pragma unroll
        for (int t = 0; t < 4; t++) {
            int idx = t * 256 + tid;
            int r = idx >> 5, pp = idx & 31;
            cpa16(&Ghs[r * 264 + pp * 8], &g_Gh[(size_t)(s0 + r) * NC + c0 + pp * 8]);
        }
        asm volatile("cp.async.commit_group;");
    };

#pragma unroll
    for (int t = 0; t < 2; t++) {
        int idx = t * 256 + tid;
        int row = idx >> 4, c2 = (idx & 15) * 2;
        *(unsigned*)&Qs[row * 40 + c2] =
            *(const unsigned*)&g_Qh[(size_t)(s0 + row) * D + h * 32 + c2];
    }
#pragma unroll
    for (int k = 0; k < 4; k++) Hs[k * 256 + tid] = 0.f;
    if (tid < 32) Zs[tid] = 0.f;

    issue_tile(0);
    __syncthreads();

    unsigned qa[2][2][4];
#pragma unroll
    for (int sh = 0; sh < 2; sh++)
#pragma unroll
        for (int ks = 0; ks < 2; ks++)
            ldm_x4(qa[sh][ks], smaddr(&Qs[(sh * 16 + l4) * 40 + ks * 16 + (lane >> 4) * 8]));

    float hacc[2][4][4] = {};
    float zmma[2][4] = {};
    const unsigned onesb[2] = {0x3C003C00u, 0x3C003C00u};

    for (int ci = 0; ci < 16; ci++) {
        int buf = (ci & 1) * 10240;
        asm volatile("cp.async.wait_group 0;" ::: "memory");
        __syncthreads();

        unsigned gf[2][4][2];
#pragma unroll
        for (int sh = 0; sh < 2; sh++)
#pragma unroll
            for (int nt = 0; nt < 4; nt++)
                ldm_x2(gf[sh][nt][0], gf[sh][nt][1],
                       smaddr(&Ghs[(sh * 16 + l4) * 264 + cw + nt * 8]));
        __syncthreads();
        if (ci < 15) issue_tile(ci + 1);

#pragma unroll
        for (int sh = 0; sh < 2; sh++) {
            unsigned pa[2][4];
#pragma unroll
            for (int nt = 0; nt < 4; nt++) {
                float S[4] = {0.f, 0.f, 0.f, 0.f};
#pragma unroll
                for (int ks = 0; ks < 2; ks++) {
                    unsigned b[2];
                    ldm_x2(b[0], b[1],
                           smaddr(&Ks[buf + (cw + nt * 8 + (l4 & 7)) * 40 + ks * 16 + (l4 >> 3) * 8]));
                    mma16816(S, qa[sh][ks], b);
                }
                __half2 x01 = __hmul2(__floats2half2_rn(S[0], S[1]), *(__half2*)&gf[sh][nt][0]);
                __half2 x23 = __hmul2(__floats2half2_rn(S[2], S[3]), *(__half2*)&gf[sh][nt][1]);
                __half2 p01 = h2ex2(x01);
                __half2 p23 = h2ex2(x23);
                unsigned u01 = *(unsigned*)&p01, u23 = *(unsigned*)&p23;
                if ((nt & 1) == 0) { pa[nt >> 1][0] = u01; pa[nt >> 1][1] = u23; }
                else               { pa[nt >> 1][2] = u01; pa[nt >> 1][3] = u23; }
            }
#pragma unroll
            for (int ks2 = 0; ks2 < 2; ks2++)
                mma16816(zmma[sh], pa[ks2], onesb);
#pragma unroll
            for (int nt2 = 0; nt2 < 4; nt2++) {
#pragma unroll
                for (int ks2 = 0; ks2 < 2; ks2++) {
                    unsigned b[2];
                    ldm_x2_t(b[0], b[1],
                             smaddr(&Vs[buf + (cw + ks2 * 16 + l4) * 40 + nt2 * 8]));
                    mma16816(hacc[sh][nt2], pa[ks2], b);
                }
            }
        }
    }

#pragma unroll
    for (int sh = 0; sh < 2; sh++) {
        if (cc == 0) {
            atomicAdd(&Zs[sh * 16 + gr], zmma[sh][0]);
            atomicAdd(&Zs[sh * 16 + gr + 8], zmma[sh][2]);
        }
#pragma unroll
        for (int nt2 = 0; nt2 < 4; nt2++) {
            atomicAdd(&Hs[(sh * 16 + gr) * 32 + nt2 * 8 + 2 * cc],           hacc[sh][nt2][0]);
            atomicAdd(&Hs[(sh * 16 + gr) * 32 + nt2 * 8 + 2 * cc + 1],       hacc[sh][nt2][1]);
            atomicAdd(&Hs[(sh * 16 + gr + 8) * 32 + nt2 * 8 + 2 * cc],       hacc[sh][nt2][2]);
            atomicAdd(&Hs[(sh * 16 + gr + 8) * 32 + nt2 * 8 + 2 * cc + 1],   hacc[sh][nt2][3]);
        }
    }
    __syncthreads();
    if (tid < 32) g_Z[(s0 + tid) * NH + h] = Zs[tid];
#pragma unroll
    for (int k = 0; k < 4; k++) {
        int idx = k * 256 + tid;
        int row = idx >> 5, d = idx & 31;
        g_Hnew[(size_t)(s0 + row) * D + h * 32 + d] = Hs[idx] / Zs[row];
    }
}

// ---------------- attn_map by QK recompute: 32 s-rows per block ----------------
#define AT_SMEM 111104
__global__ __launch_bounds__(256, 2) void attn_recompute_kernel(float* __restrict__ AM)
{
    extern __shared__ __align__(16) char smraw[];
    __half* Ks  = (__half*)smraw;
    __half* Qs  = (__half*)(smraw + 67584);
    __half* Ghs = (__half*)(smraw + 84480);
    float*  AMs = (float*)(smraw + 93184);
    float*  iZ  = (float*)(smraw + 110080);

    const int c0 = blockIdx.x * 128;
    const int s0 = blockIdx.y * 32;
    const int tid = threadIdx.x;
    const int w = tid >> 5, lane = tid & 31;
    const int gr = lane >> 2, cc = lane & 3;
    const int l4 = lane & 15;
    const int hi8 = (lane >> 4) * 8;
    const int cw16 = w * 16;

#pragma unroll
    for (int t = 0; t < 16; t++) {
        int idx = t * 256 + tid;
        int r = idx >> 5, pp = idx & 31;
        cpa16(&Ks[r * 264 + pp * 8], &g_Kh[(size_t)(c0 + r) * D + pp * 8]);
    }
#pragma unroll
    for (int t = 0; t < 4; t++) {
        int idx = t * 256 + tid;
        int r = idx >> 5, pp = idx & 31;
        cpa16(&Qs[r * 264 + pp * 8], &g_Qh[(size_t)(s0 + r) * D + pp * 8]);
    }
#pragma unroll
    for (int t = 0; t < 2; t++) {
        int idx = t * 256 + tid;
        int r = idx >> 4, pp = idx & 15;
        cpa16(&Ghs[r * 136 + pp * 8], &g_Gh[(size_t)(s0 + r) * NC + c0 + pp * 8]);
    }
    asm volatile("cp.async.commit_group;");
    {
        int s = tid >> 3, hh = tid & 7;
        iZ[tid] = 0.125f / g_Z[(s0 + s) * NH + hh];
    }
    asm volatile("cp.async.wait_group 0;" ::: "memory");
    __syncthreads();

    unsigned gfr[2][2][2];
#pragma unroll
    for (int sh = 0; sh < 2; sh++)
#pragma unroll
        for (int nt = 0; nt < 2; nt++)
            ldm_x2(gfr[sh][nt][0], gfr[sh][nt][1],
                   smaddr(&Ghs[(sh * 16 + l4) * 136 + cw16 + nt * 8]));

    float acc[2][2][4] = {};
#pragma unroll
    for (int h = 0; h < NH; h++) {
        unsigned kb[2][4];
#pragma unroll
        for (int ks = 0; ks < 2; ks++)
            ldm_x4(kb[ks], smaddr(&Ks[(cw16 + l4) * 264 + h * 32 + ks * 16 + hi8]));
#pragma unroll
        for (int sh = 0; sh < 2; sh++) {
            unsigned qa[2][4];
#pragma unroll
            for (int ks = 0; ks < 2; ks++)
                ldm_x4(qa[ks], smaddr(&Qs[(sh * 16 + l4) * 264 + h * 32 + ks * 16 + hi8]));
            float izA = iZ[(sh * 16 + gr) * 8 + h];
            float izB = iZ[(sh * 16 + gr + 8) * 8 + h];
#pragma unroll
            for (int nt = 0; nt < 2; nt++) {
                float S[4] = {0.f, 0.f, 0.f, 0.f};
#pragma unroll
                for (int ks = 0; ks < 2; ks++) {
                    unsigned bb[2];
                    bb[0] = kb[ks][nt];
                    bb[1] = kb[ks][nt + 2];
                    mma16816(S, qa[ks], bb);
                }
                __half2 x01 = __hmul2(__floats2half2_rn(S[0], S[1]), *(__half2*)&gfr[sh][nt][0]);
                __half2 x23 = __hmul2(__floats2half2_rn(S[2], S[3]), *(__half2*)&gfr[sh][nt][1]);
                float2 f01 = __half22float2(h2ex2(x01));
                float2 f23 = __half22float2(h2ex2(x23));
                acc[sh][nt][0] += f01.x * izA;
                acc[sh][nt][1] += f01.y * izA;
                acc[sh][nt][2] += f23.x * izB;
                acc[sh][nt][3] += f23.y * izB;
            }
        }
    }

#pragma unroll
    for (int sh = 0; sh < 2; sh++)
#pragma unroll
        for (int nt = 0; nt < 2; nt++) {
            int col = cw16 + nt * 8 + 2 * cc;
            *(float2*)&AMs[(sh * 16 + gr) * 132 + col]       = make_float2(acc[sh][nt][0], acc[sh][nt][1]);
            *(float2*)&AMs[(sh * 16 + gr + 8) * 132 + col]   = make_float2(acc[sh][nt][2], acc[sh][nt][3]);
        }
    __syncthreads();
#pragma unroll
    for (int t = 0; t < 4; t++) {
        int idx = t * 256 + tid;
        int r = idx >> 5, p4 = idx & 31;
        *(float4*)&AM[(size_t)(s0 + r) * NC + c0 + p4 * 4] = *(const float4*)&AMs[r * 132 + p4 * 4];
    }
}

// ---------------- cross-attn epilogue LN ----------------
__global__ __launch_bounds__(256) void ln_ca_kernel(
    const float* __restrict__ g, const float* __restrict__ b, const float* __restrict__ fusion)
{
    int tid = threadIdx.x;
    if (blockIdx.x == 0 && tid < D) g_tok[tid] = fusion[tid];
    int warp = tid >> 5, lane = tid & 31;
    int row = blockIdx.x * 8 + warp;
    float x[8];
    float s = 0.f;
#pragma unroll
    for (int j = 0; j < 8; j++) {
        int c = lane + 32 * j;
        x[j] = g_tmp[(size_t)row * D + c] + g_HS[(size_t)row * D + c];
        s += x[j];
    }
    s = warpSum(s);
    float m = s * (1.0f / D);
    float vs = 0.f;
#pragma unroll
    for (int j = 0; j < 8; j++) { float d = x[j] - m; vs += d * d; }
    vs = warpSum(vs);
    float r = rsqrtf(vs * (1.0f / D) + 1e-5f);
#pragma unroll
    for (int j = 0; j < 8; j++) {
        int c = lane + 32 * j;
        g_tok[(size_t)(1 + row) * D + c] = (x[j] - m) * r * g[c] + b[c];
    }
}

// ---------------- fused q0 + row-0 scores + AV over tokens (per-block partials) ----------------
__global__ __launch_bounds__(256) void sa0_kernel(
    const float* __restrict__ fusion,
    const float* __restrict__ w, const float* __restrict__ bqkv)
{
    __shared__ float fs[D];
    __shared__ float q0s[D];
    __shared__ float zpart[NH];
    __shared__ float a0s[D];
    int tid = threadIdx.x;
    fs[tid] = fusion[tid];
    a0s[tid] = 0.f;
    if (tid < NH) zpart[tid] = 0.f;
    __syncthreads();
    {
        float a = bqkv[tid];
        const float* wr_ = &w[(size_t)tid * D];
        for (int c = 0; c < D; c++) a += fs[c] * wr_[c];
        q0s[tid] = a;
    }
    __syncthreads();

    int warp = tid >> 5, lane = tid & 31;
    int wtotal = gridDim.x * 8;
    const float isq = 0.17677669529663687f;
    float acc[8] = {};
    float zacc = 0.f;
    for (int u = blockIdx.x * 8 + warp; u < TT; u += wtotal) {
        float mine = 0.f;
#pragma unroll
        for (int j = 0; j < 8; j++) {
            int c = lane + 32 * j;
            float v = q0s[c] * g_k2[(size_t)u * D + c];
            v = warpSum(v);
            if (lane == j) mine = v;
        }
        float pl = __expf(mine * isq);
        if (lane < 8) zacc += pl;
        float ph = __shfl_sync(0xffffffffu, pl, lane >> 2);
        const float* vrow = &g_v2[(size_t)u * D + lane * 8];
        float4 v0 = *(const float4*)vrow;
        float4 v1 = *(const float4*)(vrow + 4);
        acc[0] += ph * v0.x; acc[1] += ph * v0.y; acc[2] += ph * v0.z; acc[3] += ph * v0.w;
        acc[4] += ph * v1.x; acc[5] += ph * v1.y; acc[6] += ph * v1.z; acc[7] += ph * v1.w;
    }
    if (lane < 8) atomicAdd(&zpart[lane], zacc);
#pragma unroll
    for (int j = 0; j < 8; j++)
        atomicAdd(&a0s[lane * 8 + j], acc[j]);
    __syncthreads();
    g_a0p[blockIdx.x][tid] = a0s[tid];
    if (tid < NH) g_Z0p[blockIdx.x][tid] = zpart[tid];
}

// ---------------- final head ----------------
__device__ __forceinline__ float blockSum256(float v, volatile float* red) {
    int lane = threadIdx.x & 31, w = threadIdx.x >> 5;
    v = warpSum(v);
    __syncthreads();
    if (lane == 0) red[w] = v;
    __syncthreads();
    float s = 0.f;
#pragma unroll
    for (int i = 0; i < 8; i++) s += red[i];
    return s;
}

__global__ __launch_bounds__(256) void final_kernel(
    const float* __restrict__ fusion,
    const float* __restrict__ mow, const float* __restrict__ mob,
    const float* __restrict__ ln1g, const float* __restrict__ ln1b,
    const float* __restrict__ w1, const float* __restrict__ b1,
    const float* __restrict__ w2, const float* __restrict__ b2,
    const float* __restrict__ ln2g, const float* __restrict__ ln2b,
    float* __restrict__ out)
{
    __shared__ float a0[D], t1[D], h1[2 * D];
    __shared__ float red[8];
    int tid = threadIdx.x;
    {
        float av = 0.f, zv = 0.f;
        int hh = tid >> 5;
#pragma unroll
        for (int b = 0; b < SA0_BLOCKS; b++) {
            av += g_a0p[b][tid];
            zv += g_Z0p[b][hh];
        }
        a0[tid] = av / zv;
    }
    __syncthreads();
    float y = mob[tid];
    for (int j = 0; j < D; j++) y += a0[j] * mow[(size_t)tid * D + j];
    float tv = fusion[tid] + y;
    float m = blockSum256(tv, red) * (1.0f / D);
    float d = tv - m;
    float var = blockSum256(d * d, red) * (1.0f / D);
    float t = d * rsqrtf(var + 1e-5f) * ln1g[tid] + ln1b[tid];
    t1[tid] = t;
    __syncthreads();
    float hh2[2];
#pragma unroll
    for (int r2 = 0; r2 < 2; r2++) {
        int jj = tid + r2 * 256;
        float a = b1[jj];
        for (int c = 0; c < D; c++) a += t1[c] * w1[(size_t)jj * D + c];
        hh2[r2] = a * 0.5f * (1.f + erff(a * 0.70710678118654752f));
    }
    h1[tid] = hh2[0];
    h1[tid + 256] = hh2[1];
    __syncthreads();
    float o = b2[tid];
    for (int j = 0; j < 512; j++) o += h1[j] * w2[(size_t)tid * 512 + j];
    float t2v = t1[tid] + o;   // residual = LN1 output
    float m2 = blockSum256(t2v, red) * (1.0f / D);
    float d2 = t2v - m2;
    float v2 = blockSum256(d2 * d2, red) * (1.0f / D);
    out[tid] = d2 * rsqrtf(v2 + 1e-5f) * ln2g[tid] + ln2b[tid];
}

// ---------------- launcher ----------------
extern "C" void kernel_launch(void* const* d_in, const int* in_sizes, int n_in,
                              void* d_out, int out_size)
{
    const float* H_S     = (const float*)d_in[0];
    const float* H_C     = (const float*)d_in[1];
    const float* H_G     = (const float*)d_in[2];
    const float* G_glyph = (const float*)d_in[3];
    const float* Ws      = (const float*)d_in[4];
    const float* bs      = (const float*)d_in[5];
    const float* Wb      = (const float*)d_in[6];
    const float* bb      = (const float*)d_in[7];
    const float* Wg      = (const float*)d_in[8];
    const float* bg      = (const float*)d_in[9];
    const float* WQ      = (const float*)d_in[10];
    const float* WK      = (const float*)d_in[11];
    const float* WV      = (const float*)d_in[12];
    const float* WO      = (const float*)d_in[13];
    const float* bO      = (const float*)d_in[14];
    const float* ln_ca_g = (const float*)d_in[15];
    const float* ln_ca_b = (const float*)d_in[16];
    const float* fusion  = (const float*)d_in[17];
    const float* mha_in_w  = (const float*)d_in[18];
    const float* mha_in_b  = (const float*)d_in[19];
    const float* mha_out_w = (const float*)d_in[20];
    const float* mha_out_b = (const float*)d_in[21];
    const float* ln1_g   = (const float*)d_in[22];
    const float* ln1_b   = (const float*)d_in[23];
    const float* ln2_g   = (const float*)d_in[24];
    const float* ln2_b   = (const float*)d_in[25];
    const float* ffn_w1  = (const float*)d_in[26];
    const float* ffn_b1  = (const float*)d_in[27];
    const float* ffn_w2  = (const float*)d_in[28];
    const float* ffn_b2  = (const float*)d_in[29];

    float* out = (float*)d_out;
    float* z_fused  = out;        // 256
    float* attn_map = out + D;    // 2048 * 4096

    float *pHS, *pHC, *pHnew, *pTmp, *pTok, *pk2, *pv2;
    __half *pQh, *pKh, *pVh, *pGh;
    cudaGetSymbolAddress((void**)&pHS,  g_HS);
    cudaGetSymbolAddress((void**)&pHC,  g_HC);
    cudaGetSymbolAddress((void**)&pQh,  g_Qh);
    cudaGetSymbolAddress((void**)&pKh,  g_Kh);
    cudaGetSymbolAddress((void**)&pVh,  g_Vh);
    cudaGetSymbolAddress((void**)&pGh,  g_Gh);
    cudaGetSymbolAddress((void**)&pHnew,g_Hnew);
    cudaGetSymbolAddress((void**)&pTmp, g_tmp);
    cudaGetSymbolAddress((void**)&pTok, g_tok);
    cudaGetSymbolAddress((void**)&pk2,  g_k2);
    cudaGetSymbolAddress((void**)&pv2,  g_v2);

    static bool attrSet = false;
    static cudaStream_t s1;
    static cudaEvent_t evFork, evJoin;
    if (!attrSet) {
        cudaFuncSetAttribute(ca_fused_kernel,
                             cudaFuncAttributeMaxDynamicSharedMemorySize, CA_SMEM);
        cudaFuncSetAttribute(attn_recompute_kernel,
                             cudaFuncAttributeMaxDynamicSharedMemorySize, AT_SMEM);
        int loPri, hiPri;
        cudaDeviceGetStreamPriorityRange(&loPri, &hiPri);
        cudaStreamCreateWithPriority(&s1, cudaStreamNonBlocking, loPri);
        cudaEventCreateWithFlags(&evFork, cudaEventDisableTiming);
        cudaEventCreateWithFlags(&evJoin, cudaEventDisableTiming);
        attrSet = true;
    }

    // #1 HS (z0) + HG (z1) + HC (z2) + gate conversion (z3)
    gemm16_kernel<0><<<dim3(4, 64, 4), 256>>>(
        H_S, Ws, bs, pHS, nullptr, NS,
        H_G, Wg, bg, pTok + (size_t)(1 + NS) * D, nullptr, NG,
        H_C, Wb, bb, pHC, nullptr, NC, D, 128, 64, 256, G_glyph, pGh);
    // #2 Q/K/V triple (fp16 out)
    gemm16_kernel<1><<<dim3(4, 64, 3), 256>>>(
        pHS, WQ, nullptr, nullptr, pQh, NS,
        pHC, WK, nullptr, nullptr, pKh, NC,
        pHC, WV, nullptr, nullptr, pVh, NC, D, 256, 256, 256, nullptr, nullptr);
    // #3 fused gated cross attention (Z + Hnew)
    ca_fused_kernel<<<dim3(NH, NS / 32), 256, CA_SMEM>>>();

    cudaEventRecord(evFork, (cudaStream_t)0);

    // main chain (stream 0)
    gemm16_kernel<0><<<dim3(4, 32), 256>>>(
        pHnew, WO, bO, pTmp, nullptr, NS,
        pHnew, WO, bO, pTmp, nullptr, NS,
        pHnew, WO, bO, pTmp, nullptr, NS, D, 256, 256, 256, nullptr, nullptr);
    ln_ca_kernel<<<NS / 8, 256>>>(ln_ca_g, ln_ca_b, fusion);
    gemm16_kernel<0><<<dim3(4, 65, 2), 256>>>(
        pTok, mha_in_w + 256 * 256, mha_in_b + 256, pk2, nullptr, TT,
        pTok, mha_in_w + 512 * 256, mha_in_b + 512, pv2, nullptr, TT,
        pTok, mha_in_w + 256 * 256, mha_in_b + 256, pk2, nullptr, TT, D, 256, 256, 256, nullptr, nullptr);
    sa0_kernel<<<SA0_BLOCKS, 256>>>(fusion, mha_in_w, mha_in_b);
    final_kernel<<<1, 256>>>(fusion, mha_out_w, mha_out_b, ln1_g, ln1_b,
                             ffn_w1, ffn_b1, ffn_w2, ffn_b2, ln2_g, ln2_b, z_fused);

    // low-priority attn_map recompute backfills idle SMs
    cudaStreamWaitEvent(s1, evFork, 0);
    attn_recompute_kernel<<<dim3(NC / 128, NS / 32), 256, AT_SMEM, s1>>>(attn_map);
    cudaEventRecord(evJoin, s1);
    cudaStreamWaitEvent((cudaStream_t)0, evJoin, 0);
}